// round 1
// baseline (speedup 1.0000x reference)
#include <cuda_runtime.h>
#include <cstddef>

// ---------------------------------------------------------------------------
// InternVL2.5 Attention: B=8, N=1025, C=3200, H=25, D=128
//   qkv = x @ qkv_w + qkv_b
//   q,k = rmsnorm over full C; q *= D^-0.5
//   S[b,h] = q k^T ; P = softmax(S) ; O = P v
//   out = O @ proj_w + proj_b
// Round 0: fp32 SIMT pipeline (precision-safe baseline).
// ---------------------------------------------------------------------------

namespace {
constexpr int kB = 8, kN = 1025, kC = 3200, kH = 25, kD = 128;
constexpr int kM = kB * kN;          // 8200 rows
constexpr int kQKVN = 3 * kC;        // 9600
constexpr float kScale = 0.08838834764831845f;  // D^-0.5
constexpr float kEps = 1e-6f;

constexpr int BM = 128, BN = 128, BK = 8, TM = 8, TN = 8;
}  // namespace

// Scratch (allocation-free rule: __device__ globals)
__device__ float g_qkv[(size_t)8200 * 9600];          // 315 MB
__device__ float g_attn[(size_t)200 * 1025 * 1025];   // 840 MB
__device__ float g_ao[(size_t)8200 * 3200];           // 105 MB

// ---------------------------------------------------------------------------
// Shared-tile inner product: 8x8 per-thread outer products, float4 LDS reads.
// Smem rows padded by 4 floats -> conflict-free STS, 16B-aligned LDS.128.
// ---------------------------------------------------------------------------
__device__ __forceinline__ void mm_tile(const float (&As)[BK][BM + 4],
                                        const float (&Bs)[BK][BN + 4],
                                        int tRow, int tCol,
                                        float (&acc)[TM][TN]) {
#pragma unroll
    for (int kk = 0; kk < BK; kk++) {
        float4 a0 = *(const float4*)&As[kk][tRow * TM];
        float4 a1 = *(const float4*)&As[kk][tRow * TM + 4];
        float4 b0 = *(const float4*)&Bs[kk][tCol * TN];
        float4 b1 = *(const float4*)&Bs[kk][tCol * TN + 4];
        float ra[8] = {a0.x, a0.y, a0.z, a0.w, a1.x, a1.y, a1.z, a1.w};
        float rb[8] = {b0.x, b0.y, b0.z, b0.w, b1.x, b1.y, b1.z, b1.w};
#pragma unroll
        for (int i = 0; i < 8; i++)
#pragma unroll
            for (int j = 0; j < 8; j++) acc[i][j] += ra[i] * rb[j];
    }
}

// ---------------------------------------------------------------------------
// Generic NN SGEMM with bias: C = A[MxK] * B[KxN] + bias  (row-major)
// ---------------------------------------------------------------------------
__global__ __launch_bounds__(256, 2)
void sgemm_nn_kernel(int M, int N, int K,
                     const float* __restrict__ A, int lda,
                     const float* __restrict__ B, int ldb,
                     const float* __restrict__ bias,
                     float* __restrict__ C, int ldc) {
    __shared__ __align__(16) float As[BK][BM + 4];
    __shared__ __align__(16) float Bs[BK][BN + 4];
    const int tid = threadIdx.x;
    const int tRow = tid >> 4;
    const int tCol = tid & 15;
    const int rowBase = blockIdx.y * BM;
    const int colBase = blockIdx.x * BN;

    float acc[TM][TN] = {};

    for (int k0 = 0; k0 < K; k0 += BK) {
#pragma unroll
        for (int i = 0; i < 4; i++) {
            int idx = tid + i * 256;
            int m = idx >> 3, kk = idx & 7;
            int gr = rowBase + m, gc = k0 + kk;
            As[kk][m] = (gr < M && gc < K) ? A[(size_t)gr * lda + gc] : 0.f;
        }
#pragma unroll
        for (int i = 0; i < 4; i++) {
            int idx = tid + i * 256;
            int kk = idx >> 7, n = idx & 127;
            int gr = k0 + kk, gc = colBase + n;
            Bs[kk][n] = (gr < K && gc < N) ? B[(size_t)gr * ldb + gc] : 0.f;
        }
        __syncthreads();
        mm_tile(As, Bs, tRow, tCol, acc);
        __syncthreads();
    }

#pragma unroll
    for (int i = 0; i < TM; i++) {
        int gr = rowBase + tRow * TM + i;
        if (gr >= M) continue;
#pragma unroll
        for (int j = 0; j < TN; j++) {
            int gc = colBase + tCol * TN + j;
            if (gc < N) C[(size_t)gr * ldc + gc] = acc[i][j] + bias[gc];
        }
    }
}

// ---------------------------------------------------------------------------
// RMSNorm over full C=3200 on q and k slices of g_qkv; folds attn scale into q.
// grid: (8200, 2)   block: 256
// ---------------------------------------------------------------------------
__global__ void rmsnorm_kernel(const float* __restrict__ w_q,
                               const float* __restrict__ w_k) {
    const int m = blockIdx.x;
    const int which = blockIdx.y;  // 0 = q, 1 = k
    float* row = g_qkv + (size_t)m * kQKVN + which * kC;
    const float* w = which ? w_k : w_q;

    float ss = 0.f;
    for (int c = threadIdx.x; c < kC; c += 256) {
        float v = row[c];
        ss += v * v;
    }
#pragma unroll
    for (int o = 16; o > 0; o >>= 1) ss += __shfl_xor_sync(0xffffffffu, ss, o);
    __shared__ float sred[8];
    __shared__ float stot;
    int wid = threadIdx.x >> 5, lane = threadIdx.x & 31;
    if (lane == 0) sred[wid] = ss;
    __syncthreads();
    if (wid == 0) {
        float t = (lane < 8) ? sred[lane] : 0.f;
#pragma unroll
        for (int o = 4; o > 0; o >>= 1) t += __shfl_xor_sync(0xffffffffu, t, o);
        if (lane == 0) stot = t;
    }
    __syncthreads();
    float inv = rsqrtf(stot / (float)kC + kEps) * (which == 0 ? kScale : 1.f);
    for (int c = threadIdx.x; c < kC; c += 256) row[c] = row[c] * inv * w[c];
}

// ---------------------------------------------------------------------------
// S[b,h] = q_bh (1025x128) @ k_bh^T (128x1025)     grid: (9, 9, 200)
// ---------------------------------------------------------------------------
__global__ __launch_bounds__(256, 2)
void qk_kernel() {
    const int bh = blockIdx.z;
    const int b = bh / kH, h = bh % kH;
    const float* qb = g_qkv + (size_t)b * kN * kQKVN + h * kD;
    const float* kb = qb + kC;
    float* Cb = g_attn + (size_t)bh * kN * kN;

    __shared__ __align__(16) float As[BK][BM + 4];
    __shared__ __align__(16) float Bs[BK][BN + 4];
    const int tid = threadIdx.x;
    const int tRow = tid >> 4;
    const int tCol = tid & 15;
    const int rowBase = blockIdx.y * BM;
    const int colBase = blockIdx.x * BN;

    float acc[TM][TN] = {};

    for (int k0 = 0; k0 < kD; k0 += BK) {
#pragma unroll
        for (int i = 0; i < 4; i++) {
            int idx = tid + i * 256;
            int m = idx >> 3, kk = idx & 7;
            int gr = rowBase + m;
            As[kk][m] = (gr < kN) ? qb[(size_t)gr * kQKVN + k0 + kk] : 0.f;
            int n = m;  // same decomposition for B (NT layout)
            int gc = colBase + n;
            Bs[kk][n] = (gc < kN) ? kb[(size_t)gc * kQKVN + k0 + kk] : 0.f;
        }
        __syncthreads();
        mm_tile(As, Bs, tRow, tCol, acc);
        __syncthreads();
    }

#pragma unroll
    for (int i = 0; i < TM; i++) {
        int gr = rowBase + tRow * TM + i;
        if (gr >= kN) continue;
#pragma unroll
        for (int j = 0; j < TN; j++) {
            int gc = colBase + tCol * TN + j;
            if (gc < kN) Cb[(size_t)gr * kN + gc] = acc[i][j];
        }
    }
}

// ---------------------------------------------------------------------------
// Row softmax over 1025 elems.  grid: (1025, 200)  block: 128
// Values kept in registers: one read + one write of the 840 MB tensor.
// ---------------------------------------------------------------------------
__global__ void softmax_kernel() {
    float* p = g_attn + ((size_t)blockIdx.y * kN + blockIdx.x) * kN;
    const int tid = threadIdx.x;
    float v[9];
    float mx = -1e30f;
#pragma unroll
    for (int i = 0; i < 9; i++) {
        int c = tid + i * 128;
        v[i] = (c < kN) ? p[c] : -1e30f;
        mx = fmaxf(mx, v[i]);
    }
#pragma unroll
    for (int o = 16; o > 0; o >>= 1) mx = fmaxf(mx, __shfl_xor_sync(0xffffffffu, mx, o));
    __shared__ float sredA[4];
    __shared__ float sbcA;
    int wid = tid >> 5, lane = tid & 31;
    if (lane == 0) sredA[wid] = mx;
    __syncthreads();
    if (wid == 0) {
        float t = (lane < 4) ? sredA[lane] : -1e30f;
#pragma unroll
        for (int o = 2; o > 0; o >>= 1) t = fmaxf(t, __shfl_xor_sync(0xffffffffu, t, o));
        if (lane == 0) sbcA = t;
    }
    __syncthreads();
    mx = sbcA;

    float s = 0.f;
#pragma unroll
    for (int i = 0; i < 9; i++) {
        v[i] = __expf(v[i] - mx);  // padded lanes: exp(-huge) -> 0
        s += v[i];
    }
#pragma unroll
    for (int o = 16; o > 0; o >>= 1) s += __shfl_xor_sync(0xffffffffu, s, o);
    __shared__ float sredB[4];
    __shared__ float sbcB;
    if (lane == 0) sredB[wid] = s;
    __syncthreads();
    if (wid == 0) {
        float t = (lane < 4) ? sredB[lane] : 0.f;
#pragma unroll
        for (int o = 2; o > 0; o >>= 1) t += __shfl_xor_sync(0xffffffffu, t, o);
        if (lane == 0) sbcB = t;
    }
    __syncthreads();
    float inv = 1.f / sbcB;
#pragma unroll
    for (int i = 0; i < 9; i++) {
        int c = tid + i * 128;
        if (c < kN) p[c] = v[i] * inv;
    }
}

// ---------------------------------------------------------------------------
// O[b,:,h,:] = P[b,h] (1025x1025) @ v_bh (1025x128)   grid: (1, 9, 200)
// Output scattered into g_ao as [B,N,H*D] so proj GEMM is a plain NN GEMM.
// ---------------------------------------------------------------------------
__global__ __launch_bounds__(256, 2)
void av_kernel() {
    const int bh = blockIdx.z;
    const int b = bh / kH, h = bh % kH;
    const float* P = g_attn + (size_t)bh * kN * kN;
    const float* Vb = g_qkv + (size_t)b * kN * kQKVN + 2 * kC + h * kD;
    float* Ob = g_ao + (size_t)b * kN * kC + h * kD;

    __shared__ __align__(16) float As[BK][BM + 4];
    __shared__ __align__(16) float Bs[BK][BN + 4];
    const int tid = threadIdx.x;
    const int tRow = tid >> 4;
    const int tCol = tid & 15;
    const int rowBase = blockIdx.y * BM;

    float acc[TM][TN] = {};

    for (int k0 = 0; k0 < kN; k0 += BK) {
#pragma unroll
        for (int i = 0; i < 4; i++) {
            int idx = tid + i * 256;
            int m = idx >> 3, kk = idx & 7;
            int gr = rowBase + m, gk = k0 + kk;
            As[kk][m] = (gr < kN && gk < kN) ? P[(size_t)gr * kN + gk] : 0.f;
        }
#pragma unroll
        for (int i = 0; i < 4; i++) {
            int idx = tid + i * 256;
            int kk = idx >> 7, n = idx & 127;
            int gk = k0 + kk;
            Bs[kk][n] = (gk < kN) ? Vb[(size_t)gk * kQKVN + n] : 0.f;
        }
        __syncthreads();
        mm_tile(As, Bs, tRow, tCol, acc);
        __syncthreads();
    }

#pragma unroll
    for (int i = 0; i < TM; i++) {
        int gr = rowBase + tRow * TM + i;
        if (gr >= kN) continue;
#pragma unroll
        for (int j = 0; j < TN; j++) {
            int gc = tCol * TN + j;  // always < 128
            Ob[(size_t)gr * kC + gc] = acc[i][j];
        }
    }
}

// ---------------------------------------------------------------------------
extern "C" void kernel_launch(void* const* d_in, const int* in_sizes, int n_in,
                              void* d_out, int out_size) {
    const float* x      = (const float*)d_in[0];
    const float* qkv_w  = (const float*)d_in[1];
    const float* qkv_b  = (const float*)d_in[2];
    const float* q_norm = (const float*)d_in[3];
    const float* k_norm = (const float*)d_in[4];
    const float* proj_w = (const float*)d_in[5];
    const float* proj_b = (const float*)d_in[6];
    float* out = (float*)d_out;

    float *qkv_s = nullptr;
    cudaGetSymbolAddress((void**)&qkv_s, g_qkv);

    // 1) qkv = x @ qkv_w + qkv_b    [8200 x 9600], K=3200
    {
        dim3 grid((kQKVN + BN - 1) / BN, (kM + BM - 1) / BM);
        sgemm_nn_kernel<<<grid, 256>>>(kM, kQKVN, kC, x, kC, qkv_w, kQKVN,
                                       qkv_b, qkv_s, kQKVN);
    }
    // 2) rmsnorm on q and k (scale folded into q)
    rmsnorm_kernel<<<dim3(kM, 2), 256>>>(q_norm, k_norm);
    // 3) S = q k^T per (b,h)
    qk_kernel<<<dim3(9, 9, kB * kH), 256>>>();
    // 4) softmax rows
    softmax_kernel<<<dim3(kN, kB * kH), 128>>>();
    // 5) O = P v per (b,h)
    av_kernel<<<dim3(1, 9, kB * kH), 256>>>();
    // 6) out = O @ proj_w + proj_b   [8200 x 3200], K=3200
    {
        float* ao_s = nullptr;
        cudaGetSymbolAddress((void**)&ao_s, g_ao);
        dim3 grid((kC + BN - 1) / BN, (kM + BM - 1) / BM);
        sgemm_nn_kernel<<<grid, 256>>>(kM, kC, kC, ao_s, kC, proj_w, kC,
                                       proj_b, out, kC);
    }
}

// round 7
// speedup vs baseline: 2.5800x; 2.5800x over previous
#include <cuda_runtime.h>
#include <cuda_bf16.h>
#include <cstdint>
#include <cstddef>

// ---------------------------------------------------------------------------
// InternVL2.5 Attention: B=8, N=1025, C=3200, H=25, D=128
// Round 4: dense GEMMs on mma.sync bf16 (3-product fp32 emulation);
// tcgen05 is unavailable (harness targets compute_103 virtual arch).
// ---------------------------------------------------------------------------

namespace {
constexpr int kB = 8, kN = 1025, kC = 3200, kH = 25, kD = 128;
constexpr int kM = kB * kN;          // 8200
constexpr int kQKVN = 3 * kC;        // 9600
constexpr float kScale = 0.08838834764831845f;
constexpr float kEps = 1e-6f;

// SIMT attention tiles
constexpr int BM = 128, BN = 128, BK = 8, TM = 8, TN = 8;

// mma.sync GEMM config
constexpr int GBM = 128, GBN = 128, GBK = 64;
constexpr int TILE_B = GBM * GBK * 2;          // 16 KB per tensor tile
constexpr int STAGE_B = 4 * TILE_B;            // Ah, Al, Bh, Bl = 64 KB
constexpr int TC_SMEM = 2 * STAGE_B;           // double buffer = 128 KB
}  // namespace

// ---------------- scratch (__device__ globals; no allocation allowed) -------
__device__ float g_qkv[(size_t)8200 * 9600];          // 315 MB
__device__ float g_attn[(size_t)200 * 1025 * 1025];   // 840 MB
__device__ float g_ao[(size_t)8200 * 3200];           // 105 MB
__device__ __nv_bfloat16 g_xh[26240000], g_xl[26240000];
__device__ __nv_bfloat16 g_w1h[30720000], g_w1l[30720000];  // qkv_w^T [9600x3200]
__device__ __nv_bfloat16 g_w2h[10240000], g_w2l[10240000];  // proj_w^T [3200x3200]
__device__ __nv_bfloat16 g_aoh[26240000], g_aol[26240000];

// ---------------- PTX helpers ----------------------------------------------
__device__ __forceinline__ uint32_t smem_u32(const void* p) {
    uint32_t a;
    asm("{ .reg .u64 t; cvta.to.shared.u64 t, %1; cvt.u32.u64 %0, t; }"
        : "=r"(a) : "l"(p));
    return a;
}
__device__ __forceinline__ void ldsm_x4(uint32_t (&r)[4], uint32_t addr) {
    asm volatile("ldmatrix.sync.aligned.m8n8.x4.shared.b16 {%0,%1,%2,%3}, [%4];"
                 : "=r"(r[0]), "=r"(r[1]), "=r"(r[2]), "=r"(r[3]) : "r"(addr));
}
__device__ __forceinline__ void ldsm_x2(uint32_t (&r)[2], uint32_t addr) {
    asm volatile("ldmatrix.sync.aligned.m8n8.x2.shared.b16 {%0,%1}, [%2];"
                 : "=r"(r[0]), "=r"(r[1]) : "r"(addr));
}
__device__ __forceinline__ void mma_bf16(float (&d)[4], const uint32_t (&a)[4],
                                         const uint32_t (&b)[2]) {
    asm volatile(
        "mma.sync.aligned.m16n8k16.row.col.f32.bf16.bf16.f32 "
        "{%0,%1,%2,%3}, {%4,%5,%6,%7}, {%8,%9}, {%0,%1,%2,%3};"
        : "+f"(d[0]), "+f"(d[1]), "+f"(d[2]), "+f"(d[3])
        : "r"(a[0]), "r"(a[1]), "r"(a[2]), "r"(a[3]), "r"(b[0]), "r"(b[1]));
}
__device__ __forceinline__ uint32_t swz(uint32_t off) {
    return off ^ ((off >> 3) & 0x70);
}

// ---------------------------------------------------------------------------
// HMMA GEMM:  C[M,N] = Ahl[M,K] * (Bhl[N,K])^T + bias
// A,B as bf16 hi/lo split pairs, K-major rows. K % 64 == 0, N % 128 == 0.
// ---------------------------------------------------------------------------
__global__ __launch_bounds__(256, 1)
void mma_gemm_kernel(const __nv_bfloat16* __restrict__ Ah,
                     const __nv_bfloat16* __restrict__ Al,
                     const __nv_bfloat16* __restrict__ Bh,
                     const __nv_bfloat16* __restrict__ Bl,
                     const float* __restrict__ bias,
                     float* __restrict__ C,
                     int M, int N, int K) {
    extern __shared__ __align__(1024) char smem[];
    const uint32_t sm0 = smem_u32(smem);
    const int tid = threadIdx.x;
    const int lane = tid & 31;
    const int warp = tid >> 5;
    const int mw = warp >> 2;        // 0..1
    const int nw = warp & 3;         // 0..3
    const int rowBase = blockIdx.y * GBM;
    const int colBase = blockIdx.x * GBN;
    const int m0 = mw * 64;
    const int n0 = nw * 32;
    const int nChunks = K / GBK;

    float acc[4][4][4] = {};

    auto load_stage = [&](int c) {
        const uint32_t sb = sm0 + (uint32_t)(c & 1) * STAGE_B;
        const int k0 = c * GBK;
#pragma unroll
        for (int t = 0; t < 16; t++) {
            int cid = tid + (t << 8);
            int tensor = cid >> 10;          // 0:Ah 1:Al 2:Bh 3:Bl
            int r = (cid >> 3) & 127;
            int ck = cid & 7;
            bool isA = tensor < 2;
            int g0 = (isA ? rowBase : colBase) + r;
            int lim = isA ? M : N;
            int sz = (g0 < lim) ? 16 : 0;
            int ga = (g0 < lim) ? g0 : 0;
            const __nv_bfloat16* bp = (tensor == 0) ? Ah : (tensor == 1) ? Al
                                      : (tensor == 2) ? Bh : Bl;
            const void* gp = bp + (size_t)ga * K + k0 + (ck << 3);
            uint32_t off = (uint32_t)((r << 7) + (ck << 4));
            uint32_t d = sb + tensor * TILE_B + swz(off);
            asm volatile("cp.async.cg.shared.global [%0], [%1], 16, %2;"
                         :: "r"(d), "l"(gp), "r"(sz));
        }
        asm volatile("cp.async.commit_group;" ::: "memory");
    };

    auto compute_stage = [&](int s) {
        const uint32_t sb = sm0 + (uint32_t)s * STAGE_B;
        const uint32_t aRowA = (uint32_t)(m0 + (lane & 15));
        const uint32_t aByteHalf = (uint32_t)((lane >> 4) << 4);
        const uint32_t bRow = (uint32_t)(n0 + (lane & 7));
        const uint32_t bByteHalf = (uint32_t)(((lane >> 3) & 1) << 4);
#pragma unroll
        for (int ks = 0; ks < 4; ks++) {
            const uint32_t kb = (uint32_t)(ks << 5);
            uint32_t bh[4][2], bl[4][2];
#pragma unroll
            for (int nf = 0; nf < 4; nf++) {
                uint32_t off = (((bRow + nf * 8) << 7) + kb + bByteHalf);
                uint32_t sa = swz(off);
                ldsm_x2(bh[nf], sb + 2 * TILE_B + sa);
                ldsm_x2(bl[nf], sb + 3 * TILE_B + sa);
            }
#pragma unroll
            for (int mf = 0; mf < 4; mf++) {
                uint32_t off = (((aRowA + mf * 16) << 7) + kb + aByteHalf);
                uint32_t sa = swz(off);
                uint32_t a[4];
                ldsm_x4(a, sb + sa);                 // Ah
#pragma unroll
                for (int nf = 0; nf < 4; nf++) {
                    mma_bf16(acc[mf][nf], a, bh[nf]);
                    mma_bf16(acc[mf][nf], a, bl[nf]);
                }
                ldsm_x4(a, sb + TILE_B + sa);        // Al
#pragma unroll
                for (int nf = 0; nf < 4; nf++)
                    mma_bf16(acc[mf][nf], a, bh[nf]);
            }
        }
    };

    load_stage(0);
    for (int c = 0; c < nChunks; c++) {
        if (c + 1 < nChunks) {
            load_stage(c + 1);
            asm volatile("cp.async.wait_group 1;" ::: "memory");
        } else {
            asm volatile("cp.async.wait_group 0;" ::: "memory");
        }
        __syncthreads();
        compute_stage(c & 1);
        __syncthreads();
    }

    // epilogue: d0,d1 -> (r0, col..col+1); d2,d3 -> (r0+8, ...)
#pragma unroll
    for (int mf = 0; mf < 4; mf++) {
        int r0 = rowBase + m0 + mf * 16 + (lane >> 2);
#pragma unroll
        for (int nf = 0; nf < 4; nf++) {
            int col = colBase + n0 + nf * 8 + ((lane & 3) << 1);
            float2 bv = *(const float2*)&bias[col];
            if (r0 < M) {
                float2 o = {acc[mf][nf][0] + bv.x, acc[mf][nf][1] + bv.y};
                *(float2*)&C[(size_t)r0 * N + col] = o;
            }
            if (r0 + 8 < M) {
                float2 o = {acc[mf][nf][2] + bv.x, acc[mf][nf][3] + bv.y};
                *(float2*)&C[(size_t)(r0 + 8) * N + col] = o;
            }
        }
    }
}

// ---------------------------------------------------------------------------
// fp32 -> bf16 hi/lo split (elementwise)
// ---------------------------------------------------------------------------
__global__ void split_kernel(const float* __restrict__ src,
                             __nv_bfloat16* __restrict__ h,
                             __nv_bfloat16* __restrict__ l, int n4) {
    int i = blockIdx.x * blockDim.x + threadIdx.x;
    if (i >= n4) return;
    float4 v = ((const float4*)src)[i];
    __nv_bfloat162 h01, h23, l01, l23;
    __nv_bfloat16 hb;
    hb = __float2bfloat16(v.x); h01.x = hb; l01.x = __float2bfloat16(v.x - __bfloat162float(hb));
    hb = __float2bfloat16(v.y); h01.y = hb; l01.y = __float2bfloat16(v.y - __bfloat162float(hb));
    hb = __float2bfloat16(v.z); h23.x = hb; l23.x = __float2bfloat16(v.z - __bfloat162float(hb));
    hb = __float2bfloat16(v.w); h23.y = hb; l23.y = __float2bfloat16(v.w - __bfloat162float(hb));
    ((__nv_bfloat162*)h)[i * 2] = h01; ((__nv_bfloat162*)h)[i * 2 + 1] = h23;
    ((__nv_bfloat162*)l)[i * 2] = l01; ((__nv_bfloat162*)l)[i * 2 + 1] = l23;
}

// transpose + split: src[K,N] fp32 -> th/tl [N,K] bf16.  (K,N multiples of 32)
__global__ void tsplit_kernel(const float* __restrict__ src,
                              __nv_bfloat16* __restrict__ th,
                              __nv_bfloat16* __restrict__ tl, int K, int N) {
    __shared__ float t[32][33];
    int n0 = blockIdx.x * 32, k0 = blockIdx.y * 32;
    int tx = threadIdx.x, ty = threadIdx.y;  // 32 x 8
#pragma unroll
    for (int i = 0; i < 32; i += 8)
        t[ty + i][tx] = src[(size_t)(k0 + ty + i) * N + n0 + tx];
    __syncthreads();
#pragma unroll
    for (int i = 0; i < 32; i += 8) {
        float v = t[tx][ty + i];
        __nv_bfloat16 hb = __float2bfloat16(v);
        size_t o = (size_t)(n0 + ty + i) * K + k0 + tx;
        th[o] = hb;
        tl[o] = __float2bfloat16(v - __bfloat162float(hb));
    }
}

// ---------------------------------------------------------------------------
// SIMT attention chain (round-1 proven code)
// ---------------------------------------------------------------------------
__device__ __forceinline__ void mm_tile(const float (&As)[BK][BM + 4],
                                        const float (&Bs)[BK][BN + 4],
                                        int tRow, int tCol,
                                        float (&acc)[TM][TN]) {
#pragma unroll
    for (int kk = 0; kk < BK; kk++) {
        float4 a0 = *(const float4*)&As[kk][tRow * TM];
        float4 a1 = *(const float4*)&As[kk][tRow * TM + 4];
        float4 b0 = *(const float4*)&Bs[kk][tCol * TN];
        float4 b1 = *(const float4*)&Bs[kk][tCol * TN + 4];
        float ra[8] = {a0.x, a0.y, a0.z, a0.w, a1.x, a1.y, a1.z, a1.w};
        float rb[8] = {b0.x, b0.y, b0.z, b0.w, b1.x, b1.y, b1.z, b1.w};
#pragma unroll
        for (int i = 0; i < 8; i++)
#pragma unroll
            for (int j = 0; j < 8; j++) acc[i][j] += ra[i] * rb[j];
    }
}

__global__ void rmsnorm_kernel(const float* __restrict__ w_q,
                               const float* __restrict__ w_k) {
    const int m = blockIdx.x;
    const int which = blockIdx.y;
    float* row = g_qkv + (size_t)m * kQKVN + which * kC;
    const float* w = which ? w_k : w_q;

    float ss = 0.f;
    for (int c = threadIdx.x; c < kC; c += 256) {
        float v = row[c];
        ss += v * v;
    }
#pragma unroll
    for (int o = 16; o > 0; o >>= 1) ss += __shfl_xor_sync(0xffffffffu, ss, o);
    __shared__ float sred[8];
    __shared__ float stot;
    int wid = threadIdx.x >> 5, lane = threadIdx.x & 31;
    if (lane == 0) sred[wid] = ss;
    __syncthreads();
    if (wid == 0) {
        float t = (lane < 8) ? sred[lane] : 0.f;
#pragma unroll
        for (int o = 4; o > 0; o >>= 1) t += __shfl_xor_sync(0xffffffffu, t, o);
        if (lane == 0) stot = t;
    }
    __syncthreads();
    float inv = rsqrtf(stot / (float)kC + kEps) * (which == 0 ? kScale : 1.f);
    for (int c = threadIdx.x; c < kC; c += 256) row[c] = row[c] * inv * w[c];
}

__global__ __launch_bounds__(256, 2)
void qk_kernel() {
    const int bh = blockIdx.z;
    const int b = bh / kH, h = bh % kH;
    const float* qb = g_qkv + (size_t)b * kN * kQKVN + h * kD;
    const float* kb = qb + kC;
    float* Cb = g_attn + (size_t)bh * kN * kN;

    __shared__ __align__(16) float As[BK][BM + 4];
    __shared__ __align__(16) float Bs[BK][BN + 4];
    const int tid = threadIdx.x;
    const int tRow = tid >> 4;
    const int tCol = tid & 15;
    const int rowBase = blockIdx.y * BM;
    const int colBase = blockIdx.x * BN;

    float acc[TM][TN] = {};

    for (int k0 = 0; k0 < kD; k0 += BK) {
#pragma unroll
        for (int i = 0; i < 4; i++) {
            int idx = tid + i * 256;
            int m = idx >> 3, kk = idx & 7;
            int gr = rowBase + m;
            As[kk][m] = (gr < kN) ? qb[(size_t)gr * kQKVN + k0 + kk] : 0.f;
            int gc = colBase + m;
            Bs[kk][m] = (gc < kN) ? kb[(size_t)gc * kQKVN + k0 + kk] : 0.f;
        }
        __syncthreads();
        mm_tile(As, Bs, tRow, tCol, acc);
        __syncthreads();
    }

#pragma unroll
    for (int i = 0; i < TM; i++) {
        int gr = rowBase + tRow * TM + i;
        if (gr >= kN) continue;
#pragma unroll
        for (int j = 0; j < TN; j++) {
            int gc = colBase + tCol * TN + j;
            if (gc < kN) Cb[(size_t)gr * kN + gc] = acc[i][j];
        }
    }
}

__global__ void softmax_kernel() {
    float* p = g_attn + ((size_t)blockIdx.y * kN + blockIdx.x) * kN;
    const int tid = threadIdx.x;
    float v[9];
    float mx = -1e30f;
#pragma unroll
    for (int i = 0; i < 9; i++) {
        int c = tid + i * 128;
        v[i] = (c < kN) ? p[c] : -1e30f;
        mx = fmaxf(mx, v[i]);
    }
#pragma unroll
    for (int o = 16; o > 0; o >>= 1) mx = fmaxf(mx, __shfl_xor_sync(0xffffffffu, mx, o));
    __shared__ float sredA[4];
    __shared__ float sbcA;
    int wid = tid >> 5, lane = tid & 31;
    if (lane == 0) sredA[wid] = mx;
    __syncthreads();
    if (wid == 0) {
        float t = (lane < 4) ? sredA[lane] : -1e30f;
#pragma unroll
        for (int o = 2; o > 0; o >>= 1) t = fmaxf(t, __shfl_xor_sync(0xffffffffu, t, o));
        if (lane == 0) sbcA = t;
    }
    __syncthreads();
    mx = sbcA;

    float s = 0.f;
#pragma unroll
    for (int i = 0; i < 9; i++) {
        v[i] = __expf(v[i] - mx);
        s += v[i];
    }
#pragma unroll
    for (int o = 16; o > 0; o >>= 1) s += __shfl_xor_sync(0xffffffffu, s, o);
    __shared__ float sredB[4];
    __shared__ float sbcB;
    if (lane == 0) sredB[wid] = s;
    __syncthreads();
    if (wid == 0) {
        float t = (lane < 4) ? sredB[lane] : 0.f;
#pragma unroll
        for (int o = 2; o > 0; o >>= 1) t += __shfl_xor_sync(0xffffffffu, t, o);
        if (lane == 0) sbcB = t;
    }
    __syncthreads();
    float inv = 1.f / sbcB;
#pragma unroll
    for (int i = 0; i < 9; i++) {
        int c = tid + i * 128;
        if (c < kN) p[c] = v[i] * inv;
    }
}

__global__ __launch_bounds__(256, 2)
void av_kernel() {
    const int bh = blockIdx.z;
    const int b = bh / kH, h = bh % kH;
    const float* P = g_attn + (size_t)bh * kN * kN;
    const float* Vb = g_qkv + (size_t)b * kN * kQKVN + 2 * kC + h * kD;
    float* Ob = g_ao + (size_t)b * kN * kC + h * kD;

    __shared__ __align__(16) float As[BK][BM + 4];
    __shared__ __align__(16) float Bs[BK][BN + 4];
    const int tid = threadIdx.x;
    const int tRow = tid >> 4;
    const int tCol = tid & 15;
    const int rowBase = blockIdx.y * BM;

    float acc[TM][TN] = {};

    for (int k0 = 0; k0 < kN; k0 += BK) {
#pragma unroll
        for (int i = 0; i < 4; i++) {
            int idx = tid + i * 256;
            int m = idx >> 3, kk = idx & 7;
            int gr = rowBase + m, gk = k0 + kk;
            As[kk][m] = (gr < kN && gk < kN) ? P[(size_t)gr * kN + gk] : 0.f;
        }
#pragma unroll
        for (int i = 0; i < 4; i++) {
            int idx = tid + i * 256;
            int kk = idx >> 7, n = idx & 127;
            int gk = k0 + kk;
            Bs[kk][n] = (gk < kN) ? Vb[(size_t)gk * kQKVN + n] : 0.f;
        }
        __syncthreads();
        mm_tile(As, Bs, tRow, tCol, acc);
        __syncthreads();
    }

#pragma unroll
    for (int i = 0; i < TM; i++) {
        int gr = rowBase + tRow * TM + i;
        if (gr >= kN) continue;
#pragma unroll
        for (int j = 0; j < TN; j++) {
            int gc = tCol * TN + j;
            Ob[(size_t)gr * kC + gc] = acc[i][j];
        }
    }
}

// ---------------------------------------------------------------------------
extern "C" void kernel_launch(void* const* d_in, const int* in_sizes, int n_in,
                              void* d_out, int out_size) {
    const float* x      = (const float*)d_in[0];
    const float* qkv_w  = (const float*)d_in[1];
    const float* qkv_b  = (const float*)d_in[2];
    const float* q_norm = (const float*)d_in[3];
    const float* k_norm = (const float*)d_in[4];
    const float* proj_w = (const float*)d_in[5];
    const float* proj_b = (const float*)d_in[6];
    float* out = (float*)d_out;

    float *qkv_s, *ao_s;
    __nv_bfloat16 *xh, *xl, *w1h, *w1l, *w2h, *w2l, *aoh, *aol;
    cudaGetSymbolAddress((void**)&qkv_s, g_qkv);
    cudaGetSymbolAddress((void**)&ao_s, g_ao);
    cudaGetSymbolAddress((void**)&xh, g_xh);
    cudaGetSymbolAddress((void**)&xl, g_xl);
    cudaGetSymbolAddress((void**)&w1h, g_w1h);
    cudaGetSymbolAddress((void**)&w1l, g_w1l);
    cudaGetSymbolAddress((void**)&w2h, g_w2h);
    cudaGetSymbolAddress((void**)&w2l, g_w2l);
    cudaGetSymbolAddress((void**)&aoh, g_aoh);
    cudaGetSymbolAddress((void**)&aol, g_aol);

    cudaFuncSetAttribute(mma_gemm_kernel,
                         cudaFuncAttributeMaxDynamicSharedMemorySize, TC_SMEM);

    const int n4 = kM * kC / 4;
    // prep: splits + weight transposes
    split_kernel<<<(n4 + 255) / 256, 256>>>(x, xh, xl, n4);
    tsplit_kernel<<<dim3(kQKVN / 32, kC / 32), dim3(32, 8)>>>(qkv_w, w1h, w1l, kC, kQKVN);
    tsplit_kernel<<<dim3(kC / 32, kC / 32), dim3(32, 8)>>>(proj_w, w2h, w2l, kC, kC);

    // 1) qkv GEMM (HMMA)
    mma_gemm_kernel<<<dim3(kQKVN / GBN, (kM + GBM - 1) / GBM), 256, TC_SMEM>>>(
        xh, xl, w1h, w1l, qkv_b, qkv_s, kM, kQKVN, kC);
    // 2) rmsnorm q/k
    rmsnorm_kernel<<<dim3(kM, 2), 256>>>(q_norm, k_norm);
    // 3-5) attention chain
    qk_kernel<<<dim3(9, 9, kB * kH), 256>>>();
    softmax_kernel<<<dim3(kN, kB * kH), 128>>>();
    av_kernel<<<dim3(1, 9, kB * kH), 256>>>();
    // 6) proj GEMM (HMMA)
    split_kernel<<<(n4 + 255) / 256, 256>>>(ao_s, aoh, aol, n4);
    mma_gemm_kernel<<<dim3(kC / GBN, (kM + GBM - 1) / GBM), 256, TC_SMEM>>>(
        aoh, aol, w2h, w2l, proj_b, out, kM, kC, kC);
}

// round 8
// speedup vs baseline: 3.6458x; 1.4131x over previous
#include <cuda_runtime.h>
#include <cuda_bf16.h>
#include <cstdint>
#include <cstddef>

// ---------------------------------------------------------------------------
// InternVL2.5 Attention: B=8, N=1025, C=3200, H=25, D=128
// Round 8: ALL GEMMs (qkv, qk^T, pv, proj) on mma.sync bf16 3-product fp32
// emulation. rmsnorm emits q/k bf16 splits; softmax emits P bf16 splits.
// ---------------------------------------------------------------------------

namespace {
constexpr int kB = 8, kN = 1025, kC = 3200, kH = 25, kD = 128;
constexpr int kM = kB * kN;          // 8200
constexpr int kQKVN = 3 * kC;        // 9600
constexpr int kSld = 1032;           // S row stride (even -> float2-aligned)
constexpr int kKP = 1088;            // padded attention-K (17*64)
constexpr float kScale = 0.08838834764831845f;
constexpr float kEps = 1e-6f;

// mma.sync GEMM config
constexpr int GBM = 128, GBN = 128, GBK = 64;
constexpr int TILE_B = GBM * GBK * 2;          // 16 KB per tensor tile
constexpr int STAGE_B = 4 * TILE_B;            // Ah, Al, Bh, Bl = 64 KB
constexpr int TC_SMEM = 2 * STAGE_B;           // double buffer = 128 KB
}  // namespace

// ---------------- scratch (__device__ globals; no allocation allowed) -------
__device__ float g_qkv[(size_t)8200 * 9600];              // 315 MB
__device__ float g_attn[(size_t)200 * 1025 * kSld];       // 846 MB (S scores)
__device__ float g_ao[(size_t)8200 * 3200];               // 105 MB
__device__ __nv_bfloat16 g_xh[26240000], g_xl[26240000];
__device__ __nv_bfloat16 g_w1h[30720000], g_w1l[30720000];  // qkv_w^T
__device__ __nv_bfloat16 g_w2h[10240000], g_w2l[10240000];  // proj_w^T
__device__ __nv_bfloat16 g_aoh[26240000], g_aol[26240000];
__device__ __nv_bfloat16 g_qh[26240000], g_ql[26240000];    // q split [8200,3200]
__device__ __nv_bfloat16 g_kh[26240000], g_kl[26240000];    // k split [8200,3200]
__device__ __nv_bfloat16 g_ph[(size_t)200 * 1025 * kKP];    // P split  446 MB
__device__ __nv_bfloat16 g_pl[(size_t)200 * 1025 * kKP];
__device__ __nv_bfloat16 g_vth[(size_t)200 * 128 * kKP];    // V^T split 55.7 MB
__device__ __nv_bfloat16 g_vtl[(size_t)200 * 128 * kKP];

// ---------------- PTX helpers ----------------------------------------------
__device__ __forceinline__ uint32_t smem_u32(const void* p) {
    uint32_t a;
    asm("{ .reg .u64 t; cvta.to.shared.u64 t, %1; cvt.u32.u64 %0, t; }"
        : "=r"(a) : "l"(p));
    return a;
}
__device__ __forceinline__ void ldsm_x4(uint32_t (&r)[4], uint32_t addr) {
    asm volatile("ldmatrix.sync.aligned.m8n8.x4.shared.b16 {%0,%1,%2,%3}, [%4];"
                 : "=r"(r[0]), "=r"(r[1]), "=r"(r[2]), "=r"(r[3]) : "r"(addr));
}
__device__ __forceinline__ void ldsm_x2(uint32_t (&r)[2], uint32_t addr) {
    asm volatile("ldmatrix.sync.aligned.m8n8.x2.shared.b16 {%0,%1}, [%2];"
                 : "=r"(r[0]), "=r"(r[1]) : "r"(addr));
}
__device__ __forceinline__ void mma_bf16(float (&d)[4], const uint32_t (&a)[4],
                                         const uint32_t (&b)[2]) {
    asm volatile(
        "mma.sync.aligned.m16n8k16.row.col.f32.bf16.bf16.f32 "
        "{%0,%1,%2,%3}, {%4,%5,%6,%7}, {%8,%9}, {%0,%1,%2,%3};"
        : "+f"(d[0]), "+f"(d[1]), "+f"(d[2]), "+f"(d[3])
        : "r"(a[0]), "r"(a[1]), "r"(a[2]), "r"(a[3]), "r"(b[0]), "r"(b[1]));
}
__device__ __forceinline__ uint32_t swz(uint32_t off) {
    return off ^ ((off >> 3) & 0x70);
}

// ---------------------------------------------------------------------------
// Shared HMMA GEMM core:  C[M,N] = Ahl[M,K] * (Bhl[N,K])^T (+ bias)
// A rows stride lda, B rows stride ldb, C rows stride ldc. K % 64 == 0.
// Out-of-range A/B rows zero-filled (cp.async size-0 trick).
// ---------------------------------------------------------------------------
__device__ __forceinline__ void gemm_core(
    const __nv_bfloat16* __restrict__ Ah, const __nv_bfloat16* __restrict__ Al,
    const __nv_bfloat16* __restrict__ Bh, const __nv_bfloat16* __restrict__ Bl,
    const float* __restrict__ bias, float* __restrict__ C,
    int M, int N, int K, int lda, int ldb, int ldc,
    int rowBase, int colBase, uint32_t sm0) {
    const int tid = threadIdx.x;
    const int lane = tid & 31;
    const int warp = tid >> 5;
    const int m0 = (warp >> 2) * 64;
    const int n0 = (warp & 3) * 32;
    const int nChunks = K / GBK;

    float acc[4][4][4] = {};

    auto load_stage = [&](int c) {
        const uint32_t sb = sm0 + (uint32_t)(c & 1) * STAGE_B;
        const int k0 = c * GBK;
#pragma unroll
        for (int t = 0; t < 16; t++) {
            int cid = tid + (t << 8);
            int tensor = cid >> 10;          // 0:Ah 1:Al 2:Bh 3:Bl
            int r = (cid >> 3) & 127;
            int ck = cid & 7;
            bool isA = tensor < 2;
            int g0 = (isA ? rowBase : colBase) + r;
            int lim = isA ? M : N;
            int sz = (g0 < lim) ? 16 : 0;
            int ga = (g0 < lim) ? g0 : 0;
            int ld = isA ? lda : ldb;
            const __nv_bfloat16* bp = (tensor == 0) ? Ah : (tensor == 1) ? Al
                                      : (tensor == 2) ? Bh : Bl;
            const void* gp = bp + (size_t)ga * ld + k0 + (ck << 3);
            uint32_t off = (uint32_t)((r << 7) + (ck << 4));
            uint32_t d = sb + tensor * TILE_B + swz(off);
            asm volatile("cp.async.cg.shared.global [%0], [%1], 16, %2;"
                         :: "r"(d), "l"(gp), "r"(sz));
        }
        asm volatile("cp.async.commit_group;" ::: "memory");
    };

    auto compute_stage = [&](int s) {
        const uint32_t sb = sm0 + (uint32_t)s * STAGE_B;
        const uint32_t aRowA = (uint32_t)(m0 + (lane & 15));
        const uint32_t aByteHalf = (uint32_t)((lane >> 4) << 4);
        const uint32_t bRow = (uint32_t)(n0 + (lane & 7));
        const uint32_t bByteHalf = (uint32_t)(((lane >> 3) & 1) << 4);
#pragma unroll
        for (int ks = 0; ks < 4; ks++) {
            const uint32_t kb = (uint32_t)(ks << 5);
            uint32_t bh[4][2], bl[4][2];
#pragma unroll
            for (int nf = 0; nf < 4; nf++) {
                uint32_t off = (((bRow + nf * 8) << 7) + kb + bByteHalf);
                uint32_t sa = swz(off);
                ldsm_x2(bh[nf], sb + 2 * TILE_B + sa);
                ldsm_x2(bl[nf], sb + 3 * TILE_B + sa);
            }
#pragma unroll
            for (int mf = 0; mf < 4; mf++) {
                uint32_t off = (((aRowA + mf * 16) << 7) + kb + aByteHalf);
                uint32_t sa = swz(off);
                uint32_t a[4];
                ldsm_x4(a, sb + sa);                 // Ah
#pragma unroll
                for (int nf = 0; nf < 4; nf++) {
                    mma_bf16(acc[mf][nf], a, bh[nf]);
                    mma_bf16(acc[mf][nf], a, bl[nf]);
                }
                ldsm_x4(a, sb + TILE_B + sa);        // Al
#pragma unroll
                for (int nf = 0; nf < 4; nf++)
                    mma_bf16(acc[mf][nf], a, bh[nf]);
            }
        }
    };

    load_stage(0);
    for (int c = 0; c < nChunks; c++) {
        if (c + 1 < nChunks) {
            load_stage(c + 1);
            asm volatile("cp.async.wait_group 1;" ::: "memory");
        } else {
            asm volatile("cp.async.wait_group 0;" ::: "memory");
        }
        __syncthreads();
        compute_stage(c & 1);
        __syncthreads();
    }

#pragma unroll
    for (int mf = 0; mf < 4; mf++) {
        int r0 = rowBase + m0 + mf * 16 + (lane >> 2);
#pragma unroll
        for (int nf = 0; nf < 4; nf++) {
            int col = colBase + n0 + nf * 8 + ((lane & 3) << 1);
            float bx = 0.f, by = 0.f;
            if (bias && col + 1 < N) { float2 bv = *(const float2*)&bias[col]; bx = bv.x; by = bv.y; }
            if (r0 < M) {
                if (col + 1 < N) {
                    float2 o = {acc[mf][nf][0] + bx, acc[mf][nf][1] + by};
                    *(float2*)&C[(size_t)r0 * ldc + col] = o;
                } else if (col < N) {
                    C[(size_t)r0 * ldc + col] = acc[mf][nf][0] + bx;
                }
            }
            if (r0 + 8 < M) {
                if (col + 1 < N) {
                    float2 o = {acc[mf][nf][2] + bx, acc[mf][nf][3] + by};
                    *(float2*)&C[(size_t)(r0 + 8) * ldc + col] = o;
                } else if (col < N) {
                    C[(size_t)(r0 + 8) * ldc + col] = acc[mf][nf][2] + bx;
                }
            }
        }
    }
}

// ---- dense GEMM (qkv / proj) ----------------------------------------------
__global__ __launch_bounds__(256, 1)
void mma_gemm_kernel(const __nv_bfloat16* __restrict__ Ah,
                     const __nv_bfloat16* __restrict__ Al,
                     const __nv_bfloat16* __restrict__ Bh,
                     const __nv_bfloat16* __restrict__ Bl,
                     const float* __restrict__ bias,
                     float* __restrict__ C, int M, int N, int K) {
    extern __shared__ __align__(1024) char smem[];
    gemm_core(Ah, Al, Bh, Bl, bias, C, M, N, K, K, K, N,
              blockIdx.y * GBM, blockIdx.x * GBN, smem_u32(smem));
}

// ---- batched S = q k^T  grid (9, 9, 200) ----------------------------------
__global__ __launch_bounds__(256, 1)
void qk_mma_kernel() {
    extern __shared__ __align__(1024) char smem[];
    const int bh = blockIdx.z;
    const int b = bh / kH, h = bh % kH;
    const size_t qoff = (size_t)b * kN * kC + h * kD;
    float* S = g_attn + (size_t)bh * kN * kSld;
    gemm_core(g_qh + qoff, g_ql + qoff, g_kh + qoff, g_kl + qoff,
              nullptr, S, kN, kN, kD, kC, kC, kSld,
              blockIdx.y * GBM, blockIdx.x * GBN, smem_u32(smem));
}

// ---- batched O = P v  grid (1, 9, 200) -------------------------------------
__global__ __launch_bounds__(256, 1)
void av_mma_kernel() {
    extern __shared__ __align__(1024) char smem[];
    const int bh = blockIdx.z;
    const int b = bh / kH, h = bh % kH;
    const size_t poff = (size_t)bh * kN * kKP;
    const size_t voff = (size_t)bh * kD * kKP;
    float* O = g_ao + (size_t)b * kN * kC + h * kD;
    gemm_core(g_ph + poff, g_pl + poff, g_vth + voff, g_vtl + voff,
              nullptr, O, kN, kD, kKP, kKP, kKP, kC,
              blockIdx.y * GBM, 0, smem_u32(smem));
}

// ---------------------------------------------------------------------------
// fp32 -> bf16 hi/lo split (elementwise)
// ---------------------------------------------------------------------------
__global__ void split_kernel(const float* __restrict__ src,
                             __nv_bfloat16* __restrict__ h,
                             __nv_bfloat16* __restrict__ l, int n4) {
    int i = blockIdx.x * blockDim.x + threadIdx.x;
    if (i >= n4) return;
    float4 v = ((const float4*)src)[i];
    __nv_bfloat162 h01, h23, l01, l23;
    __nv_bfloat16 hb;
    hb = __float2bfloat16(v.x); h01.x = hb; l01.x = __float2bfloat16(v.x - __bfloat162float(hb));
    hb = __float2bfloat16(v.y); h01.y = hb; l01.y = __float2bfloat16(v.y - __bfloat162float(hb));
    hb = __float2bfloat16(v.z); h23.x = hb; l23.x = __float2bfloat16(v.z - __bfloat162float(hb));
    hb = __float2bfloat16(v.w); h23.y = hb; l23.y = __float2bfloat16(v.w - __bfloat162float(hb));
    ((__nv_bfloat162*)h)[i * 2] = h01; ((__nv_bfloat162*)h)[i * 2 + 1] = h23;
    ((__nv_bfloat162*)l)[i * 2] = l01; ((__nv_bfloat162*)l)[i * 2 + 1] = l23;
}

// transpose + split: src[K,N] fp32 -> th/tl [N,K] bf16.  (K,N multiples of 32)
__global__ void tsplit_kernel(const float* __restrict__ src,
                              __nv_bfloat16* __restrict__ th,
                              __nv_bfloat16* __restrict__ tl, int K, int N) {
    __shared__ float t[32][33];
    int n0 = blockIdx.x * 32, k0 = blockIdx.y * 32;
    int tx = threadIdx.x, ty = threadIdx.y;  // 32 x 8
#pragma unroll
    for (int i = 0; i < 32; i += 8)
        t[ty + i][tx] = src[(size_t)(k0 + ty + i) * N + n0 + tx];
    __syncthreads();
#pragma unroll
    for (int i = 0; i < 32; i += 8) {
        float v = t[tx][ty + i];
        __nv_bfloat16 hb = __float2bfloat16(v);
        size_t o = (size_t)(n0 + ty + i) * K + k0 + tx;
        th[o] = hb;
        tl[o] = __float2bfloat16(v - __bfloat162float(hb));
    }
}

// per-(b,h) V transpose+split: V[1025,128] -> Vt[128, kKP] zero-padded.
// grid: (kKP/32=34, 128/32=4, 200)  block: (32, 8)
__global__ void vtsplit_kernel() {
    __shared__ float t[32][33];
    const int bh = blockIdx.z;
    const int b = bh / kH, h = bh % kH;
    const float* V = g_qkv + (size_t)b * kN * kQKVN + 2 * kC + h * kD;
    const int k0 = blockIdx.x * 32, n0 = blockIdx.y * 32;
    const int tx = threadIdx.x, ty = threadIdx.y;
#pragma unroll
    for (int i = 0; i < 32; i += 8) {
        int kk = k0 + ty + i;
        t[ty + i][tx] = (kk < kN) ? V[(size_t)kk * kQKVN + n0 + tx] : 0.f;
    }
    __syncthreads();
    __nv_bfloat16* th = g_vth + (size_t)bh * kD * kKP;
    __nv_bfloat16* tl = g_vtl + (size_t)bh * kD * kKP;
#pragma unroll
    for (int i = 0; i < 32; i += 8) {
        float v = t[tx][ty + i];
        __nv_bfloat16 hb = __float2bfloat16(v);
        size_t o = (size_t)(n0 + ty + i) * kKP + k0 + tx;
        th[o] = hb;
        tl[o] = __float2bfloat16(v - __bfloat162float(hb));
    }
}

// ---------------------------------------------------------------------------
// RMSNorm over C=3200 on q,k slices of g_qkv -> bf16 hi/lo splits.
// q gets attn scale folded in.  grid: (8200, 2)  block: 256
// ---------------------------------------------------------------------------
__global__ void rmsnorm_kernel(const float* __restrict__ w_q,
                               const float* __restrict__ w_k) {
    const int m = blockIdx.x;
    const int which = blockIdx.y;
    const float* row = g_qkv + (size_t)m * kQKVN + which * kC;
    const float* w = which ? w_k : w_q;
    __nv_bfloat16* dh = (which ? g_kh : g_qh) + (size_t)m * kC;
    __nv_bfloat16* dl = (which ? g_kl : g_ql) + (size_t)m * kC;

    float ss = 0.f;
    for (int c = threadIdx.x; c < kC; c += 256) {
        float v = row[c];
        ss += v * v;
    }
#pragma unroll
    for (int o = 16; o > 0; o >>= 1) ss += __shfl_xor_sync(0xffffffffu, ss, o);
    __shared__ float sred[8];
    __shared__ float stot;
    int wid = threadIdx.x >> 5, lane = threadIdx.x & 31;
    if (lane == 0) sred[wid] = ss;
    __syncthreads();
    if (wid == 0) {
        float t = (lane < 8) ? sred[lane] : 0.f;
#pragma unroll
        for (int o = 4; o > 0; o >>= 1) t += __shfl_xor_sync(0xffffffffu, t, o);
        if (lane == 0) stot = t;
    }
    __syncthreads();
    float inv = rsqrtf(stot / (float)kC + kEps) * (which == 0 ? kScale : 1.f);
    for (int c = threadIdx.x; c < kC; c += 256) {
        float v = row[c] * inv * w[c];
        __nv_bfloat16 hb = __float2bfloat16(v);
        dh[c] = hb;
        dl[c] = __float2bfloat16(v - __bfloat162float(hb));
    }
}

// ---------------------------------------------------------------------------
// Row softmax over 1025 logits; emits P as bf16 hi/lo, K-padded with zeros.
// grid: (1025, 200)  block: 128
// ---------------------------------------------------------------------------
__global__ void softmax_kernel() {
    const int bh = blockIdx.y, rowi = blockIdx.x;
    const float* p = g_attn + ((size_t)bh * kN + rowi) * kSld;
    __nv_bfloat16* ph = g_ph + ((size_t)bh * kN + rowi) * kKP;
    __nv_bfloat16* pl = g_pl + ((size_t)bh * kN + rowi) * kKP;
    const int tid = threadIdx.x;
    float v[9];
    float mx = -1e30f;
#pragma unroll
    for (int i = 0; i < 9; i++) {
        int c = tid + i * 128;
        v[i] = (c < kN) ? p[c] : -1e30f;
        mx = fmaxf(mx, v[i]);
    }
#pragma unroll
    for (int o = 16; o > 0; o >>= 1) mx = fmaxf(mx, __shfl_xor_sync(0xffffffffu, mx, o));
    __shared__ float sredA[4];
    __shared__ float sbcA;
    int wid = tid >> 5, lane = tid & 31;
    if (lane == 0) sredA[wid] = mx;
    __syncthreads();
    if (wid == 0) {
        float t = (lane < 4) ? sredA[lane] : -1e30f;
#pragma unroll
        for (int o = 2; o > 0; o >>= 1) t = fmaxf(t, __shfl_xor_sync(0xffffffffu, t, o));
        if (lane == 0) sbcA = t;
    }
    __syncthreads();
    mx = sbcA;

    float s = 0.f;
#pragma unroll
    for (int i = 0; i < 9; i++) {
        v[i] = __expf(v[i] - mx);
        s += v[i];
    }
#pragma unroll
    for (int o = 16; o > 0; o >>= 1) s += __shfl_xor_sync(0xffffffffu, s, o);
    __shared__ float sredB[4];
    __shared__ float sbcB;
    if (lane == 0) sredB[wid] = s;
    __syncthreads();
    if (wid == 0) {
        float t = (lane < 4) ? sredB[lane] : 0.f;
#pragma unroll
        for (int o = 2; o > 0; o >>= 1) t += __shfl_xor_sync(0xffffffffu, t, o);
        if (lane == 0) sbcB = t;
    }
    __syncthreads();
    float inv = 1.f / sbcB;
#pragma unroll
    for (int i = 0; i < 9; i++) {
        int c = tid + i * 128;
        if (c < kN) {
            float pv = v[i] * inv;
            __nv_bfloat16 hb = __float2bfloat16(pv);
            ph[c] = hb;
            pl[c] = __float2bfloat16(pv - __bfloat162float(hb));
        } else if (c < kKP) {
            ph[c] = __float2bfloat16(0.f);
            pl[c] = __float2bfloat16(0.f);
        }
    }
}

// ---------------------------------------------------------------------------
extern "C" void kernel_launch(void* const* d_in, const int* in_sizes, int n_in,
                              void* d_out, int out_size) {
    const float* x      = (const float*)d_in[0];
    const float* qkv_w  = (const float*)d_in[1];
    const float* qkv_b  = (const float*)d_in[2];
    const float* q_norm = (const float*)d_in[3];
    const float* k_norm = (const float*)d_in[4];
    const float* proj_w = (const float*)d_in[5];
    const float* proj_b = (const float*)d_in[6];
    float* out = (float*)d_out;

    float *qkv_s, *ao_s;
    __nv_bfloat16 *xh, *xl, *w1h, *w1l, *w2h, *w2l, *aoh, *aol;
    cudaGetSymbolAddress((void**)&qkv_s, g_qkv);
    cudaGetSymbolAddress((void**)&ao_s, g_ao);
    cudaGetSymbolAddress((void**)&xh, g_xh);
    cudaGetSymbolAddress((void**)&xl, g_xl);
    cudaGetSymbolAddress((void**)&w1h, g_w1h);
    cudaGetSymbolAddress((void**)&w1l, g_w1l);
    cudaGetSymbolAddress((void**)&w2h, g_w2h);
    cudaGetSymbolAddress((void**)&w2l, g_w2l);
    cudaGetSymbolAddress((void**)&aoh, g_aoh);
    cudaGetSymbolAddress((void**)&aol, g_aol);

    cudaFuncSetAttribute(mma_gemm_kernel,
                         cudaFuncAttributeMaxDynamicSharedMemorySize, TC_SMEM);
    cudaFuncSetAttribute(qk_mma_kernel,
                         cudaFuncAttributeMaxDynamicSharedMemorySize, TC_SMEM);
    cudaFuncSetAttribute(av_mma_kernel,
                         cudaFuncAttributeMaxDynamicSharedMemorySize, TC_SMEM);

    const int n4 = kM * kC / 4;
    // prep: splits + weight transposes
    split_kernel<<<(n4 + 255) / 256, 256>>>(x, xh, xl, n4);
    tsplit_kernel<<<dim3(kQKVN / 32, kC / 32), dim3(32, 8)>>>(qkv_w, w1h, w1l, kC, kQKVN);
    tsplit_kernel<<<dim3(kC / 32, kC / 32), dim3(32, 8)>>>(proj_w, w2h, w2l, kC, kC);

    // 1) qkv GEMM (HMMA)
    mma_gemm_kernel<<<dim3(kQKVN / GBN, (kM + GBM - 1) / GBM), 256, TC_SMEM>>>(
        xh, xl, w1h, w1l, qkv_b, qkv_s, kM, kQKVN, kC);
    // 2) rmsnorm q/k -> bf16 splits ; V transpose-split
    rmsnorm_kernel<<<dim3(kM, 2), 256>>>(q_norm, k_norm);
    vtsplit_kernel<<<dim3(kKP / 32, kD / 32, kB * kH), dim3(32, 8)>>>();
    // 3) S = q k^T (HMMA, batched)
    qk_mma_kernel<<<dim3(9, 9, kB * kH), 256, TC_SMEM>>>();
    // 4) softmax -> P bf16 splits
    softmax_kernel<<<dim3(kN, kB * kH), 128>>>();
    // 5) O = P v (HMMA, batched)
    av_mma_kernel<<<dim3(1, 9, kB * kH), 256, TC_SMEM>>>();
    // 6) proj GEMM (HMMA)
    split_kernel<<<(n4 + 255) / 256, 256>>>(ao_s, aoh, aol, n4);
    mma_gemm_kernel<<<dim3(kC / GBN, (kM + GBM - 1) / GBM), 256, TC_SMEM>>>(
        aoh, aol, w2h, w2l, proj_b, out, kM, kC, kC);
}

// round 10
// speedup vs baseline: 3.9149x; 1.0738x over previous
#include <cuda_runtime.h>
#include <cuda_bf16.h>
#include <cstdint>
#include <cstddef>

// ---------------------------------------------------------------------------
// InternVL2.5 Attention: B=8, N=1025, C=3200, H=25, D=128
// Round 9: qkv/proj on HMMA (3-product bf16 fp32-emulation) + fused
// flash-attention middle (qk + online softmax + pv in one kernel, register
// resident, no S/P materialization).
// ---------------------------------------------------------------------------

namespace {
constexpr int kB = 8, kN = 1025, kC = 3200, kH = 25, kD = 128;
constexpr int kM = kB * kN;          // 8200
constexpr int kQKVN = 3 * kC;        // 9600
constexpr int kKP = 1088;            // padded key count (17*64)
constexpr float kScale = 0.08838834764831845f;
constexpr float kEps = 1e-6f;

// mma.sync dense GEMM config
constexpr int GBM = 128, GBN = 128, GBK = 64;
constexpr int TILE_B = GBM * GBK * 2;          // 16 KB per tensor tile
constexpr int STAGE_B = 4 * TILE_B;            // Ah, Al, Bh, Bl = 64 KB
constexpr int TC_SMEM = 2 * STAGE_B;           // 128 KB

// flash kernel smem: q 64KB + 2 stages x 64KB (k 32KB + v 32KB)
constexpr int FL_SMEM = 3 * 65536;             // 192 KB
}  // namespace

// ---------------- scratch (__device__ globals; no allocation allowed) -------
__device__ float g_qkv[(size_t)8200 * 9600];                // 315 MB
__device__ __nv_bfloat16 g_xh[26240000], g_xl[26240000];
__device__ __nv_bfloat16 g_w1h[30720000], g_w1l[30720000];  // qkv_w^T
__device__ __nv_bfloat16 g_w2h[10240000], g_w2l[10240000];  // proj_w^T
__device__ __nv_bfloat16 g_aoh[26240000], g_aol[26240000];  // O splits
__device__ __nv_bfloat16 g_qh[26240000], g_ql[26240000];    // q split
__device__ __nv_bfloat16 g_kh[26240000], g_kl[26240000];    // k split
__device__ __nv_bfloat16 g_vth[(size_t)200 * 128 * kKP];    // V^T split
__device__ __nv_bfloat16 g_vtl[(size_t)200 * 128 * kKP];

// ---------------- PTX helpers ----------------------------------------------
__device__ __forceinline__ uint32_t smem_u32(const void* p) {
    uint32_t a;
    asm("{ .reg .u64 t; cvta.to.shared.u64 t, %1; cvt.u32.u64 %0, t; }"
        : "=r"(a) : "l"(p));
    return a;
}
__device__ __forceinline__ void ldsm_x4(uint32_t (&r)[4], uint32_t addr) {
    asm volatile("ldmatrix.sync.aligned.m8n8.x4.shared.b16 {%0,%1,%2,%3}, [%4];"
                 : "=r"(r[0]), "=r"(r[1]), "=r"(r[2]), "=r"(r[3]) : "r"(addr));
}
__device__ __forceinline__ void ldsm_x2(uint32_t (&r)[2], uint32_t addr) {
    asm volatile("ldmatrix.sync.aligned.m8n8.x2.shared.b16 {%0,%1}, [%2];"
                 : "=r"(r[0]), "=r"(r[1]) : "r"(addr));
}
__device__ __forceinline__ void mma_bf16(float (&d)[4], const uint32_t (&a)[4],
                                         const uint32_t (&b)[2]) {
    asm volatile(
        "mma.sync.aligned.m16n8k16.row.col.f32.bf16.bf16.f32 "
        "{%0,%1,%2,%3}, {%4,%5,%6,%7}, {%8,%9}, {%0,%1,%2,%3};"
        : "+f"(d[0]), "+f"(d[1]), "+f"(d[2]), "+f"(d[3])
        : "r"(a[0]), "r"(a[1]), "r"(a[2]), "r"(a[3]), "r"(b[0]), "r"(b[1]));
}
__device__ __forceinline__ uint32_t swz(uint32_t off) {
    return off ^ ((off >> 3) & 0x70);
}
__device__ __forceinline__ uint32_t packbf(float lo, float hi) {
    __nv_bfloat162 h;
    h.x = __float2bfloat16(lo);
    h.y = __float2bfloat16(hi);
    return *reinterpret_cast<uint32_t*>(&h);
}
__device__ __forceinline__ float bfres(float v) {
    return v - __bfloat162float(__float2bfloat16(v));
}

// ---------------------------------------------------------------------------
// HMMA dense GEMM core (proven): C[M,N] = Ahl[M,K]*(Bhl[N,K])^T + bias
// ---------------------------------------------------------------------------
__device__ __forceinline__ void gemm_core(
    const __nv_bfloat16* __restrict__ Ah, const __nv_bfloat16* __restrict__ Al,
    const __nv_bfloat16* __restrict__ Bh, const __nv_bfloat16* __restrict__ Bl,
    const float* __restrict__ bias, float* __restrict__ C,
    int M, int N, int K, int lda, int ldb, int ldc,
    int rowBase, int colBase, uint32_t sm0) {
    const int tid = threadIdx.x;
    const int lane = tid & 31;
    const int warp = tid >> 5;
    const int m0 = (warp >> 2) * 64;
    const int n0 = (warp & 3) * 32;
    const int nChunks = K / GBK;

    float acc[4][4][4] = {};

    auto load_stage = [&](int c) {
        const uint32_t sb = sm0 + (uint32_t)(c & 1) * STAGE_B;
        const int k0 = c * GBK;
#pragma unroll
        for (int t = 0; t < 16; t++) {
            int cid = tid + (t << 8);
            int tensor = cid >> 10;
            int r = (cid >> 3) & 127;
            int ck = cid & 7;
            bool isA = tensor < 2;
            int g0 = (isA ? rowBase : colBase) + r;
            int lim = isA ? M : N;
            int sz = (g0 < lim) ? 16 : 0;
            int ga = (g0 < lim) ? g0 : 0;
            int ld = isA ? lda : ldb;
            const __nv_bfloat16* bp = (tensor == 0) ? Ah : (tensor == 1) ? Al
                                      : (tensor == 2) ? Bh : Bl;
            const void* gp = bp + (size_t)ga * ld + k0 + (ck << 3);
            uint32_t off = (uint32_t)((r << 7) + (ck << 4));
            uint32_t d = sb + tensor * TILE_B + swz(off);
            asm volatile("cp.async.cg.shared.global [%0], [%1], 16, %2;"
                         :: "r"(d), "l"(gp), "r"(sz));
        }
        asm volatile("cp.async.commit_group;" ::: "memory");
    };

    auto compute_stage = [&](int s) {
        const uint32_t sb = sm0 + (uint32_t)s * STAGE_B;
        const uint32_t aRowA = (uint32_t)(m0 + (lane & 15));
        const uint32_t aByteHalf = (uint32_t)((lane >> 4) << 4);
        const uint32_t bRow = (uint32_t)(n0 + (lane & 7));
        const uint32_t bByteHalf = (uint32_t)(((lane >> 3) & 1) << 4);
#pragma unroll
        for (int ks = 0; ks < 4; ks++) {
            const uint32_t kb = (uint32_t)(ks << 5);
            uint32_t bh[4][2], bl[4][2];
#pragma unroll
            for (int nf = 0; nf < 4; nf++) {
                uint32_t off = (((bRow + nf * 8) << 7) + kb + bByteHalf);
                uint32_t sa = swz(off);
                ldsm_x2(bh[nf], sb + 2 * TILE_B + sa);
                ldsm_x2(bl[nf], sb + 3 * TILE_B + sa);
            }
#pragma unroll
            for (int mf = 0; mf < 4; mf++) {
                uint32_t off = (((aRowA + mf * 16) << 7) + kb + aByteHalf);
                uint32_t sa = swz(off);
                uint32_t a[4];
                ldsm_x4(a, sb + sa);
#pragma unroll
                for (int nf = 0; nf < 4; nf++) {
                    mma_bf16(acc[mf][nf], a, bh[nf]);
                    mma_bf16(acc[mf][nf], a, bl[nf]);
                }
                ldsm_x4(a, sb + TILE_B + sa);
#pragma unroll
                for (int nf = 0; nf < 4; nf++)
                    mma_bf16(acc[mf][nf], a, bh[nf]);
            }
        }
    };

    load_stage(0);
    for (int c = 0; c < nChunks; c++) {
        if (c + 1 < nChunks) {
            load_stage(c + 1);
            asm volatile("cp.async.wait_group 1;" ::: "memory");
        } else {
            asm volatile("cp.async.wait_group 0;" ::: "memory");
        }
        __syncthreads();
        compute_stage(c & 1);
        __syncthreads();
    }

#pragma unroll
    for (int mf = 0; mf < 4; mf++) {
        int r0 = rowBase + m0 + mf * 16 + (lane >> 2);
#pragma unroll
        for (int nf = 0; nf < 4; nf++) {
            int col = colBase + n0 + nf * 8 + ((lane & 3) << 1);
            float bx = 0.f, by = 0.f;
            if (bias && col + 1 < N) { float2 bv = *(const float2*)&bias[col]; bx = bv.x; by = bv.y; }
            if (r0 < M) {
                if (col + 1 < N) {
                    float2 o = {acc[mf][nf][0] + bx, acc[mf][nf][1] + by};
                    *(float2*)&C[(size_t)r0 * ldc + col] = o;
                } else if (col < N) {
                    C[(size_t)r0 * ldc + col] = acc[mf][nf][0] + bx;
                }
            }
            if (r0 + 8 < M) {
                if (col + 1 < N) {
                    float2 o = {acc[mf][nf][2] + bx, acc[mf][nf][3] + by};
                    *(float2*)&C[(size_t)(r0 + 8) * ldc + col] = o;
                } else if (col < N) {
                    C[(size_t)(r0 + 8) * ldc + col] = acc[mf][nf][2] + bx;
                }
            }
        }
    }
}

__global__ __launch_bounds__(256, 1)
void mma_gemm_kernel(const __nv_bfloat16* __restrict__ Ah,
                     const __nv_bfloat16* __restrict__ Al,
                     const __nv_bfloat16* __restrict__ Bh,
                     const __nv_bfloat16* __restrict__ Bl,
                     const float* __restrict__ bias,
                     float* __restrict__ C, int M, int N, int K) {
    extern __shared__ __align__(1024) char smem[];
    gemm_core(Ah, Al, Bh, Bl, bias, C, M, N, K, K, K, N,
              blockIdx.y * GBM, blockIdx.x * GBN, smem_u32(smem));
}

// ---------------------------------------------------------------------------
// Fused flash attention: grid (9 row-blocks, 200 bh), block 256.
// Warp w owns q rows [16w, 16w+16) of its 128-row block and the full key dim.
// smem: q[split][panel][128x128B] 64KB | stage s: k[split][panel][64x128B]
// 32KB + v[split][128x128B] 32KB.
// ---------------------------------------------------------------------------
__global__ __launch_bounds__(256, 1)
void flash_kernel() {
    extern __shared__ __align__(1024) char smem[];
    const uint32_t sm0 = smem_u32(smem);
    const int tid = threadIdx.x;
    const int lane = tid & 31;
    const int warp = tid >> 5;
    const int bh = blockIdx.y;
    const int b = bh / kH, h = bh % kH;
    const int rowBase = blockIdx.x * 128;
    constexpr int NIT = kKP / 64;   // 17

    const __nv_bfloat16* qsrc[2] = {g_qh, g_ql};
    const __nv_bfloat16* ksrc[2] = {g_kh, g_kl};
    const __nv_bfloat16* vsrc[2] = {g_vth, g_vtl};

    // ---- q tile loads (lumped into group 0 with kv stage 0)
#pragma unroll
    for (int t = 0; t < 16; t++) {
        int cid = tid + (t << 8);           // 0..4095
        int split = cid >> 11;
        int p = (cid >> 10) & 1;
        int r = (cid >> 3) & 127;
        int ck = cid & 7;
        int lr = rowBase + r;
        int sz = (lr < kN) ? 16 : 0;
        int gr = (lr < kN) ? lr : 0;
        const void* gp = qsrc[split] + ((size_t)(b * kN + gr)) * kC + h * kD + p * 64 + ck * 8;
        uint32_t d = sm0 + (uint32_t)(split * 32768 + p * 16384)
                   + swz((uint32_t)((r << 7) + (ck << 4)));
        asm volatile("cp.async.cg.shared.global [%0], [%1], 16, %2;"
                     :: "r"(d), "l"(gp), "r"(sz));
    }

    auto load_kv = [&](int kt) {
        const uint32_t sb = sm0 + 65536u + (uint32_t)(kt & 1) * 65536u;
#pragma unroll
        for (int t = 0; t < 16; t++) {
            int cid = tid + (t << 8);       // 0..4095
            if (cid < 2048) {               // k: [split][panel][64 rows][128B]
                int split = cid >> 10;
                int p = (cid >> 9) & 1;
                int r = (cid >> 3) & 63;
                int ck = cid & 7;
                int gk = kt * 64 + r;
                int sz = (gk < kN) ? 16 : 0;
                int gr = (gk < kN) ? gk : 0;
                const void* gp = ksrc[split] + ((size_t)(b * kN + gr)) * kC + h * kD + p * 64 + ck * 8;
                uint32_t d = sb + (uint32_t)(split * 16384 + p * 8192)
                           + swz((uint32_t)((r << 7) + (ck << 4)));
                asm volatile("cp.async.cg.shared.global [%0], [%1], 16, %2;"
                             :: "r"(d), "l"(gp), "r"(sz));
            } else {                        // v^T: [split][128 d-rows][128B]
                int cid2 = cid - 2048;
                int split = cid2 >> 10;
                int r = (cid2 >> 3) & 127;
                int ck = cid2 & 7;
                const void* gp = vsrc[split] + ((size_t)(bh * kD + r)) * kKP + kt * 64 + ck * 8;
                uint32_t d = sb + 32768u + (uint32_t)(split * 16384)
                           + swz((uint32_t)((r << 7) + (ck << 4)));
                asm volatile("cp.async.cg.shared.global [%0], [%1], 16, 16;"
                             :: "r"(d), "l"(gp));
            }
        }
        asm volatile("cp.async.commit_group;" ::: "memory");
    };

    load_kv(0);   // commits group0 = q + kv0

    uint32_t aqh[8][4], aql[8][4];
    float accO[16][4];
#pragma unroll
    for (int nd = 0; nd < 16; nd++)
        accO[nd][0] = accO[nd][1] = accO[nd][2] = accO[nd][3] = 0.f;
    float m0r = -1e30f, m1r = -1e30f, l0r = 0.f, l1r = 0.f;

    const uint32_t bRow = (uint32_t)(lane & 7);
    const uint32_t bHalf = (uint32_t)(((lane >> 3) & 1) << 4);

    for (int kt = 0; kt < NIT; kt++) {
        if (kt + 1 < NIT) {
            load_kv(kt + 1);
            asm volatile("cp.async.wait_group 1;" ::: "memory");
        } else {
            asm volatile("cp.async.wait_group 0;" ::: "memory");
        }
        __syncthreads();

        if (kt == 0) {  // preload q fragments (held in registers all iters)
            const uint32_t aRow = (uint32_t)(warp * 16 + (lane & 15));
            const uint32_t aHalf = (uint32_t)((lane >> 4) << 4);
#pragma unroll
            for (int ks = 0; ks < 8; ks++) {
                uint32_t p = (uint32_t)(ks >> 2);
                uint32_t kb = (uint32_t)((ks & 3) << 5);
                uint32_t off = swz((aRow << 7) + kb + aHalf);
                ldsm_x4(aqh[ks], sm0 + p * 16384 + off);
                ldsm_x4(aql[ks], sm0 + 32768 + p * 16384 + off);
            }
        }

        const uint32_t sb = sm0 + 65536u + (uint32_t)(kt & 1) * 65536u;

        // ---- S = q k^T : 16 rows x 64 keys per warp
        float accS[8][4];
#pragma unroll
        for (int nf = 0; nf < 8; nf++)
            accS[nf][0] = accS[nf][1] = accS[nf][2] = accS[nf][3] = 0.f;
#pragma unroll
        for (int ks = 0; ks < 8; ks++) {
            uint32_t p = (uint32_t)(ks >> 2);
            uint32_t kb = (uint32_t)((ks & 3) << 5);
#pragma unroll
            for (int nf = 0; nf < 8; nf++) {
                uint32_t off = swz((((uint32_t)(nf * 8) + bRow) << 7) + kb + bHalf);
                uint32_t bkh[2], bkl[2];
                ldsm_x2(bkh, sb + p * 8192 + off);
                ldsm_x2(bkl, sb + 16384 + p * 8192 + off);
                mma_bf16(accS[nf], aqh[ks], bkh);
                mma_bf16(accS[nf], aqh[ks], bkl);
                mma_bf16(accS[nf], aql[ks], bkh);
            }
        }

        // ---- mask invalid keys on last tile
        if (kt == NIT - 1) {
#pragma unroll
            for (int nf = 0; nf < 8; nf++) {
                int c0 = (NIT - 1) * 64 + nf * 8 + ((lane & 3) << 1);
                if (c0 >= kN)     { accS[nf][0] = -1e30f; accS[nf][2] = -1e30f; }
                if (c0 + 1 >= kN) { accS[nf][1] = -1e30f; accS[nf][3] = -1e30f; }
            }
        }

        // ---- online softmax (rows r = 16w+(lane>>2) and r+8)
        float mx0 = -1e30f, mx1 = -1e30f;
#pragma unroll
        for (int nf = 0; nf < 8; nf++) {
            mx0 = fmaxf(mx0, fmaxf(accS[nf][0], accS[nf][1]));
            mx1 = fmaxf(mx1, fmaxf(accS[nf][2], accS[nf][3]));
        }
        mx0 = fmaxf(mx0, __shfl_xor_sync(0xffffffffu, mx0, 1));
        mx0 = fmaxf(mx0, __shfl_xor_sync(0xffffffffu, mx0, 2));
        mx1 = fmaxf(mx1, __shfl_xor_sync(0xffffffffu, mx1, 1));
        mx1 = fmaxf(mx1, __shfl_xor_sync(0xffffffffu, mx1, 2));
        float mn0 = fmaxf(m0r, mx0), mn1 = fmaxf(m1r, mx1);
        float a0 = __expf(m0r - mn0), a1 = __expf(m1r - mn1);
        m0r = mn0; m1r = mn1;

        float s0 = 0.f, s1 = 0.f;
#pragma unroll
        for (int nf = 0; nf < 8; nf++) {
            accS[nf][0] = __expf(accS[nf][0] - mn0);
            accS[nf][1] = __expf(accS[nf][1] - mn0);
            accS[nf][2] = __expf(accS[nf][2] - mn1);
            accS[nf][3] = __expf(accS[nf][3] - mn1);
            s0 += accS[nf][0] + accS[nf][1];
            s1 += accS[nf][2] + accS[nf][3];
        }
        s0 += __shfl_xor_sync(0xffffffffu, s0, 1);
        s0 += __shfl_xor_sync(0xffffffffu, s0, 2);
        s1 += __shfl_xor_sync(0xffffffffu, s1, 1);
        s1 += __shfl_xor_sync(0xffffffffu, s1, 2);
        l0r = l0r * a0 + s0;
        l1r = l1r * a1 + s1;
#pragma unroll
        for (int nd = 0; nd < 16; nd++) {
            accO[nd][0] *= a0; accO[nd][1] *= a0;
            accO[nd][2] *= a1; accO[nd][3] *= a1;
        }

        // ---- O += P * V : P re-packed from C-fragments into A-fragments
#pragma unroll
        for (int j = 0; j < 4; j++) {   // key chunks of 16
            uint32_t aPh[4], aPl[4];
            const float* pA = accS[2 * j];
            const float* pB = accS[2 * j + 1];
            aPh[0] = packbf(pA[0], pA[1]);
            aPh[1] = packbf(pA[2], pA[3]);
            aPh[2] = packbf(pB[0], pB[1]);
            aPh[3] = packbf(pB[2], pB[3]);
            aPl[0] = packbf(bfres(pA[0]), bfres(pA[1]));
            aPl[1] = packbf(bfres(pA[2]), bfres(pA[3]));
            aPl[2] = packbf(bfres(pB[0]), bfres(pB[1]));
            aPl[3] = packbf(bfres(pB[2]), bfres(pB[3]));
#pragma unroll
            for (int nd = 0; nd < 16; nd++) {
                uint32_t off = swz((((uint32_t)(nd * 8) + bRow) << 7)
                                   + (uint32_t)(j * 32) + bHalf);
                uint32_t bvh[2], bvl[2];
                ldsm_x2(bvh, sb + 32768 + off);
                ldsm_x2(bvl, sb + 49152 + off);
                mma_bf16(accO[nd], aPh, bvh);
                mma_bf16(accO[nd], aPh, bvl);
                mma_bf16(accO[nd], aPl, bvh);
            }
        }
        __syncthreads();
    }

    // ---- epilogue: divide by l, write bf16 hi/lo splits for proj GEMM
    float inv0 = 1.f / l0r, inv1 = 1.f / l1r;
    int r0g = rowBase + warp * 16 + (lane >> 2);
    int r1g = r0g + 8;
#pragma unroll
    for (int nd = 0; nd < 16; nd++) {
        int d0 = nd * 8 + ((lane & 3) << 1);
        if (r0g < kN) {
            float o0 = accO[nd][0] * inv0, o1 = accO[nd][1] * inv0;
            size_t off = ((size_t)(b * kN + r0g)) * kC + h * kD + d0;
            __nv_bfloat162 hv; hv.x = __float2bfloat16(o0); hv.y = __float2bfloat16(o1);
            *reinterpret_cast<__nv_bfloat162*>(g_aoh + off) = hv;
            __nv_bfloat162 lv;
            lv.x = __float2bfloat16(o0 - __bfloat162float(hv.x));
            lv.y = __float2bfloat16(o1 - __bfloat162float(hv.y));
            *reinterpret_cast<__nv_bfloat162*>(g_aol + off) = lv;
        }
        if (r1g < kN) {
            float o0 = accO[nd][2] * inv1, o1 = accO[nd][3] * inv1;
            size_t off = ((size_t)(b * kN + r1g)) * kC + h * kD + d0;
            __nv_bfloat162 hv; hv.x = __float2bfloat16(o0); hv.y = __float2bfloat16(o1);
            *reinterpret_cast<__nv_bfloat162*>(g_aoh + off) = hv;
            __nv_bfloat162 lv;
            lv.x = __float2bfloat16(o0 - __bfloat162float(hv.x));
            lv.y = __float2bfloat16(o1 - __bfloat162float(hv.y));
            *reinterpret_cast<__nv_bfloat162*>(g_aol + off) = lv;
        }
    }
}

// ---------------------------------------------------------------------------
// fp32 -> bf16 hi/lo split (elementwise)
// ---------------------------------------------------------------------------
__global__ void split_kernel(const float* __restrict__ src,
                             __nv_bfloat16* __restrict__ h,
                             __nv_bfloat16* __restrict__ l, int n4) {
    int i = blockIdx.x * blockDim.x + threadIdx.x;
    if (i >= n4) return;
    float4 v = ((const float4*)src)[i];
    __nv_bfloat162 h01, h23, l01, l23;
    __nv_bfloat16 hb;
    hb = __float2bfloat16(v.x); h01.x = hb; l01.x = __float2bfloat16(v.x - __bfloat162float(hb));
    hb = __float2bfloat16(v.y); h01.y = hb; l01.y = __float2bfloat16(v.y - __bfloat162float(hb));
    hb = __float2bfloat16(v.z); h23.x = hb; l23.x = __float2bfloat16(v.z - __bfloat162float(hb));
    hb = __float2bfloat16(v.w); h23.y = hb; l23.y = __float2bfloat16(v.w - __bfloat162float(hb));
    ((__nv_bfloat162*)h)[i * 2] = h01; ((__nv_bfloat162*)h)[i * 2 + 1] = h23;
    ((__nv_bfloat162*)l)[i * 2] = l01; ((__nv_bfloat162*)l)[i * 2 + 1] = l23;
}

// transpose + split: src[K,N] fp32 -> th/tl [N,K] bf16
__global__ void tsplit_kernel(const float* __restrict__ src,
                              __nv_bfloat16* __restrict__ th,
                              __nv_bfloat16* __restrict__ tl, int K, int N) {
    __shared__ float t[32][33];
    int n0 = blockIdx.x * 32, k0 = blockIdx.y * 32;
    int tx = threadIdx.x, ty = threadIdx.y;  // 32 x 8
#pragma unroll
    for (int i = 0; i < 32; i += 8)
        t[ty + i][tx] = src[(size_t)(k0 + ty + i) * N + n0 + tx];
    __syncthreads();
#pragma unroll
    for (int i = 0; i < 32; i += 8) {
        float v = t[tx][ty + i];
        __nv_bfloat16 hb = __float2bfloat16(v);
        size_t o = (size_t)(n0 + ty + i) * K + k0 + tx;
        th[o] = hb;
        tl[o] = __float2bfloat16(v - __bfloat162float(hb));
    }
}

// per-(b,h) V transpose+split: V[1025,128] -> Vt[128, kKP] zero-padded
__global__ void vtsplit_kernel() {
    __shared__ float t[32][33];
    const int bh = blockIdx.z;
    const int b = bh / kH, h = bh % kH;
    const float* V = g_qkv + (size_t)b * kN * kQKVN + 2 * kC + h * kD;
    const int k0 = blockIdx.x * 32, n0 = blockIdx.y * 32;
    const int tx = threadIdx.x, ty = threadIdx.y;
#pragma unroll
    for (int i = 0; i < 32; i += 8) {
        int kk = k0 + ty + i;
        t[ty + i][tx] = (kk < kN) ? V[(size_t)kk * kQKVN + n0 + tx] : 0.f;
    }
    __syncthreads();
    __nv_bfloat16* th = g_vth + (size_t)bh * kD * kKP;
    __nv_bfloat16* tl = g_vtl + (size_t)bh * kD * kKP;
#pragma unroll
    for (int i = 0; i < 32; i += 8) {
        float v = t[tx][ty + i];
        __nv_bfloat16 hb = __float2bfloat16(v);
        size_t o = (size_t)(n0 + ty + i) * kKP + k0 + tx;
        th[o] = hb;
        tl[o] = __float2bfloat16(v - __bfloat162float(hb));
    }
}

// ---------------------------------------------------------------------------
// RMSNorm over C on q,k -> bf16 hi/lo splits; q gets attn scale folded in.
// ---------------------------------------------------------------------------
__global__ void rmsnorm_kernel(const float* __restrict__ w_q,
                               const float* __restrict__ w_k) {
    const int m = blockIdx.x;
    const int which = blockIdx.y;
    const float* row = g_qkv + (size_t)m * kQKVN + which * kC;
    const float* w = which ? w_k : w_q;
    __nv_bfloat16* dh = (which ? g_kh : g_qh) + (size_t)m * kC;
    __nv_bfloat16* dl = (which ? g_kl : g_ql) + (size_t)m * kC;

    float ss = 0.f;
    for (int c = threadIdx.x; c < kC; c += 256) {
        float v = row[c];
        ss += v * v;
    }
#pragma unroll
    for (int o = 16; o > 0; o >>= 1) ss += __shfl_xor_sync(0xffffffffu, ss, o);
    __shared__ float sred[8];
    __shared__ float stot;
    int wid = threadIdx.x >> 5, lane = threadIdx.x & 31;
    if (lane == 0) sred[wid] = ss;
    __syncthreads();
    if (wid == 0) {
        float t = (lane < 8) ? sred[lane] : 0.f;
#pragma unroll
        for (int o = 4; o > 0; o >>= 1) t += __shfl_xor_sync(0xffffffffu, t, o);
        if (lane == 0) stot = t;
    }
    __syncthreads();
    float inv = rsqrtf(stot / (float)kC + kEps) * (which == 0 ? kScale : 1.f);
    for (int c = threadIdx.x; c < kC; c += 256) {
        float v = row[c] * inv * w[c];
        __nv_bfloat16 hb = __float2bfloat16(v);
        dh[c] = hb;
        dl[c] = __float2bfloat16(v - __bfloat162float(hb));
    }
}

// ---------------------------------------------------------------------------
extern "C" void kernel_launch(void* const* d_in, const int* in_sizes, int n_in,
                              void* d_out, int out_size) {
    const float* x      = (const float*)d_in[0];
    const float* qkv_w  = (const float*)d_in[1];
    const float* qkv_b  = (const float*)d_in[2];
    const float* q_norm = (const float*)d_in[3];
    const float* k_norm = (const float*)d_in[4];
    const float* proj_w = (const float*)d_in[5];
    const float* proj_b = (const float*)d_in[6];
    float* out = (float*)d_out;

    float* qkv_s;
    __nv_bfloat16 *xh, *xl, *w1h, *w1l, *w2h, *w2l, *aoh, *aol;
    cudaGetSymbolAddress((void**)&qkv_s, g_qkv);
    cudaGetSymbolAddress((void**)&xh, g_xh);
    cudaGetSymbolAddress((void**)&xl, g_xl);
    cudaGetSymbolAddress((void**)&w1h, g_w1h);
    cudaGetSymbolAddress((void**)&w1l, g_w1l);
    cudaGetSymbolAddress((void**)&w2h, g_w2h);
    cudaGetSymbolAddress((void**)&w2l, g_w2l);
    cudaGetSymbolAddress((void**)&aoh, g_aoh);
    cudaGetSymbolAddress((void**)&aol, g_aol);

    cudaFuncSetAttribute(mma_gemm_kernel,
                         cudaFuncAttributeMaxDynamicSharedMemorySize, TC_SMEM);
    cudaFuncSetAttribute(flash_kernel,
                         cudaFuncAttributeMaxDynamicSharedMemorySize, FL_SMEM);

    const int n4 = kM * kC / 4;
    // prep: splits + weight transposes
    split_kernel<<<(n4 + 255) / 256, 256>>>(x, xh, xl, n4);
    tsplit_kernel<<<dim3(kQKVN / 32, kC / 32), dim3(32, 8)>>>(qkv_w, w1h, w1l, kC, kQKVN);
    tsplit_kernel<<<dim3(kC / 32, kC / 32), dim3(32, 8)>>>(proj_w, w2h, w2l, kC, kC);

    // 1) qkv GEMM (HMMA)
    mma_gemm_kernel<<<dim3(kQKVN / GBN, (kM + GBM - 1) / GBM), 256, TC_SMEM>>>(
        xh, xl, w1h, w1l, qkv_b, qkv_s, kM, kQKVN, kC);
    // 2) rmsnorm q/k -> bf16 splits ; V transpose-split
    rmsnorm_kernel<<<dim3(kM, 2), 256>>>(q_norm, k_norm);
    vtsplit_kernel<<<dim3(kKP / 32, kD / 32, kB * kH), dim3(32, 8)>>>();
    // 3) fused flash attention -> O bf16 splits
    flash_kernel<<<dim3(9, kB * kH), 256, FL_SMEM>>>();
    // 4) proj GEMM (HMMA)
    mma_gemm_kernel<<<dim3(kC / GBN, (kM + GBM - 1) / GBM), 256, TC_SMEM>>>(
        aoh, aol, w2h, w2l, proj_b, out, kM, kC, kC);
}